// round 5
// baseline (speedup 1.0000x reference)
#include <cuda_runtime.h>
#include <cstdint>

// TPThird: e3nn-style tensor product, Z=50000 samples.
// x1: (Z,108) = [0e:48 | 1o:10x3 | 1e:10x3], x2: (Z,9) = [0e | 1o:3 | 2e:5]
// weights: (Z,4344), out: (Z,156) = [r0e:48 | r1o:30 | r1e:30 | r0o:48]
//
// Persistent blocks, double-buffered TMA bulk copies of the per-sample
// weight blob; compute for sample k overlaps the copy of sample k+1.

#define NS 48
#define NV 10
#define WNUM 4344
#define WBYTES (WNUM * 4)
#define OUTDIM 156
#define NBLK 888           // 148 SMs x 6 resident blocks

#define OFF_W00   0
#define OFF_W01   2304
#define OFF_W10   2784
#define OFF_W110  2884
#define OFF_W112  3364
#define OFF_W12   3464
#define OFF_W20   3564
#define OFF_W211  3664
#define OFF_W213  3764
#define OFF_W22   4244

#define N0E  0.13130643285972254f   // sqrt(1/58)
#define N1O  0.19611613513818404f   // sqrt(3/78)
#define N1E  0.31622776601683794f   // sqrt(1/10)
#define N0O  0.31622776601683794f   // sqrt(1/10)
#define ISQ3 0.57735026918962576f   // 1/sqrt(3)
#define ISQ6 0.40824829046386302f   // 1/sqrt(6)
#define S10  0.31622776601683794f   // 1/sqrt(10)
#define S30  0.18257418583505537f   // 1/sqrt(30)

__device__ __forceinline__ uint32_t smem_u32(const void* p) {
    uint32_t a;
    asm("{ .reg .u64 t; cvta.to.shared.u64 t, %1; cvt.u32.u64 %0, t; }"
        : "=r"(a) : "l"(p));
    return a;
}

__device__ __forceinline__ void tma_issue(uint32_t dst, const void* src,
                                          uint32_t mbar_a) {
    asm volatile("mbarrier.arrive.expect_tx.shared.b64 _, [%0], %1;"
                 :: "r"(mbar_a), "r"((uint32_t)WBYTES) : "memory");
    asm volatile(
        "cp.async.bulk.shared::cluster.global.mbarrier::complete_tx::bytes "
        "[%0], [%1], %2, [%3];"
        :: "r"(dst), "l"(src), "r"((uint32_t)WBYTES), "r"(mbar_a)
        : "memory");
}

__device__ __forceinline__ void mbar_wait(uint32_t mbar_a, int parity) {
    asm volatile(
        "{\n\t"
        ".reg .pred P;\n\t"
        "WAIT_%=:\n\t"
        "mbarrier.try_wait.parity.acquire.cta.shared::cta.b64 P, [%0], %1, 0x989680;\n\t"
        "@!P bra WAIT_%=;\n\t"
        "}"
        :: "r"(mbar_a), "r"((uint32_t)parity) : "memory");
}

__global__ __launch_bounds__(192) void tp_third_kernel(
    const float* __restrict__ x1,
    const float* __restrict__ x2,
    const float* __restrict__ wts,
    float* __restrict__ out,
    int Z)
{
    const int t = threadIdx.x;

    __shared__ alignas(128) float sw[2][WNUM];   // 2 x 17376 B weight buffers
    __shared__ alignas(8) unsigned long long mbar[2];
    __shared__ float sx1[108];
    __shared__ float sx2[9];
    __shared__ float s_a00[48];
    __shared__ float s_a110[10];
    __shared__ float s_a213[10];
    __shared__ float s_v10[30];
    __shared__ float s_v12[30];
    __shared__ float s_v211[30];
    __shared__ float s_v112[30];
    __shared__ float s_v20[30];
    __shared__ float s_v22[30];

    const int chunk = (Z + gridDim.x - 1) / gridDim.x;
    const int sbeg  = blockIdx.x * chunk;
    const int send  = (sbeg + chunk < Z) ? (sbeg + chunk) : Z;
    const int n     = send - sbeg;
    if (n <= 0) return;

    const uint32_t mbar_a0 = smem_u32(&mbar[0]);
    const uint32_t mbar_a1 = smem_u32(&mbar[1]);
    const uint32_t sw_a0   = smem_u32(sw[0]);
    const uint32_t sw_a1   = smem_u32(sw[1]);

    if (t == 0) {
        asm volatile("mbarrier.init.shared.b64 [%0], 1;" :: "r"(mbar_a0) : "memory");
        asm volatile("mbarrier.init.shared.b64 [%0], 1;" :: "r"(mbar_a1) : "memory");
    }
    __syncthreads();

    // prologue: start copy of first sample's weights into buffer 0
    if (t == 0) {
        tma_issue(sw_a0, (const void*)(wts + (size_t)sbeg * WNUM), mbar_a0);
    }

    int ph0 = 0, ph1 = 0;

    for (int k = 0; k < n; k++) {
        const int cur = k & 1;
        const int z   = sbeg + k;

        // prefetch next sample's weights into the other buffer
        // (its previous consumer finished at iteration k-1; guarded by the
        //  trailing __syncthreads of that iteration)
        if (t == 0 && (k + 1) < n) {
            tma_issue(cur ? sw_a0 : sw_a1,
                      (const void*)(wts + (size_t)(z + 1) * WNUM),
                      cur ? mbar_a0 : mbar_a1);
        }

        // stage small inputs
        if (t < 108)       sx1[t]       = x1[(size_t)z * 108 + t];
        else if (t < 117)  sx2[t - 108] = x2[(size_t)z * 9 + (t - 108)];
        __syncthreads();

        // ---- phase 2: left-operand vectors (overlaps TMA) ----
        const float e0 = sx2[0];
        const float b0 = sx2[1], b1 = sx2[2], b2 = sx2[3];
        const float c0 = sx2[4], c1 = sx2[5], c2 = sx2[6], c3 = sx2[7], c4 = sx2[8];

        if (t < 48) {
            s_a00[t] = N0E * e0 * sx1[t];
        } else if (t < 58) {
            const int u = t - 48;
            const float a0 = sx1[48 + u * 3 + 0];
            const float a1 = sx1[48 + u * 3 + 1];
            const float a2 = sx1[48 + u * 3 + 2];
            s_a110[u] = N0E * ISQ3 * (a0 * b0 + a1 * b1 + a2 * b2);
            s_v10[u * 3 + 0] = N1O * ISQ3 * e0 * a0;
            s_v10[u * 3 + 1] = N1O * ISQ3 * e0 * a1;
            s_v10[u * 3 + 2] = N1O * ISQ3 * e0 * a2;
            s_v112[u * 3 + 0] = N1E * ISQ6 * (a1 * b2 - a2 * b1);
            s_v112[u * 3 + 1] = N1E * ISQ6 * (a2 * b0 - a0 * b2);
            s_v112[u * 3 + 2] = N1E * ISQ6 * (a0 * b1 - a1 * b0);
            const float g0 = S10 * a2 * c0 - S30 * a0 * c2 - S10 * a0 * c4 + S10 * a1 * c1;
            const float g1 = S10 * a2 * c3 + S10 * a0 * c1 + 2.0f * S30 * a1 * c2;
            const float g2 = -S30 * a2 * c2 + S10 * a2 * c4 + S10 * a0 * c0 + S10 * a1 * c3;
            s_v12[u * 3 + 0] = N1O * g0;
            s_v12[u * 3 + 1] = N1O * g1;
            s_v12[u * 3 + 2] = N1O * g2;
        } else if (t < 68) {
            const int u = t - 58;
            const float a0 = sx1[78 + u * 3 + 0];
            const float a1 = sx1[78 + u * 3 + 1];
            const float a2 = sx1[78 + u * 3 + 2];
            s_a213[u] = N0O * ISQ3 * (a0 * b0 + a1 * b1 + a2 * b2);
            s_v20[u * 3 + 0] = N1E * ISQ3 * e0 * a0;
            s_v20[u * 3 + 1] = N1E * ISQ3 * e0 * a1;
            s_v20[u * 3 + 2] = N1E * ISQ3 * e0 * a2;
            s_v211[u * 3 + 0] = N1O * ISQ6 * (a1 * b2 - a2 * b1);
            s_v211[u * 3 + 1] = N1O * ISQ6 * (a2 * b0 - a0 * b2);
            s_v211[u * 3 + 2] = N1O * ISQ6 * (a0 * b1 - a1 * b0);
            const float g0 = S10 * a2 * c0 - S30 * a0 * c2 - S10 * a0 * c4 + S10 * a1 * c1;
            const float g1 = S10 * a2 * c3 + S10 * a0 * c1 + 2.0f * S30 * a1 * c2;
            const float g2 = -S30 * a2 * c2 + S10 * a2 * c4 + S10 * a0 * c0 + S10 * a1 * c3;
            s_v22[u * 3 + 0] = N1E * g0;
            s_v22[u * 3 + 1] = N1E * g1;
            s_v22[u * 3 + 2] = N1E * g2;
        }
        __syncthreads();

        // ---- wait for this sample's weights ----
        if (cur == 0) { mbar_wait(mbar_a0, ph0); ph0 ^= 1; }
        else          { mbar_wait(mbar_a1, ph1); ph1 ^= 1; }

        const float* __restrict__ W = sw[cur];
        float* __restrict__ o = out + (size_t)z * OUTDIM;

        // ---- phase 3: column matvecs from smem, warp-aligned groups ----
        if (t < 64) {
            if (t < 48) {
                const int w = t;
                float acc = 0.0f;
                #pragma unroll
                for (int u = 0; u < 48; u++) acc += s_a00[u] * W[OFF_W00 + u * 48 + w];
                #pragma unroll
                for (int u = 0; u < 10; u++) acc += s_a110[u] * W[OFF_W110 + u * 48 + w];
                o[w] = acc;
            }
        } else if (t < 128) {
            const int w = t - 64;
            if (w < 48) {
                float acc = 0.0f;
                #pragma unroll
                for (int u = 0; u < 10; u++) acc += s_a213[u] * W[OFF_W213 + u * 48 + w];
                o[108 + w] = acc;
            }
        } else if (t < 160) {
            const int idx = t - 128;
            const int w = idx / 3, j = idx - w * 3;
            const int wc = (w > 9) ? 9 : w;
            float p = 0.0f;
            #pragma unroll
            for (int i = 0; i < 16; i++) {
                const int u = 3 * i + j;
                p += sx1[u] * W[OFF_W01 + u * 10 + wc];
            }
            const int base = w * 3;
            float ts = __shfl_sync(0xFFFFFFFFu, p, base)
                     + __shfl_sync(0xFFFFFFFFu, p, base + 1)
                     + __shfl_sync(0xFFFFFFFFu, p, base + 2);
            float acc = (N1O * ISQ3) * sx2[1 + j] * ts;
            #pragma unroll
            for (int u = 0; u < 10; u++) {
                acc += s_v10[u * 3 + j]  * W[OFF_W10  + u * 10 + wc];
                acc += s_v12[u * 3 + j]  * W[OFF_W12  + u * 10 + wc];
                acc += s_v211[u * 3 + j] * W[OFF_W211 + u * 10 + wc];
            }
            if (idx < 30) o[48 + w * 3 + j] = acc;
        } else {
            const int idx = t - 160;
            if (idx < 30) {
                const int w = idx / 3, j = idx - w * 3;
                float acc = 0.0f;
                #pragma unroll
                for (int u = 0; u < 10; u++) {
                    acc += s_v112[u * 3 + j] * W[OFF_W112 + u * 10 + w];
                    acc += s_v20[u * 3 + j]  * W[OFF_W20  + u * 10 + w];
                    acc += s_v22[u * 3 + j]  * W[OFF_W22  + u * 10 + w];
                }
                o[78 + w * 3 + j] = acc;
            }
        }

        // all reads of sw[cur], sx1, sx2 done before next iteration's
        // staging / prefetch overwrite them
        __syncthreads();
    }
}

extern "C" void kernel_launch(void* const* d_in, const int* in_sizes, int n_in,
                              void* d_out, int out_size) {
    const float* x1  = (const float*)d_in[0];
    const float* x2  = (const float*)d_in[1];
    const float* wts = (const float*)d_in[2];
    float* out = (float*)d_out;
    const int Z = in_sizes[0] / 108;
    const int grid = (Z < NBLK) ? Z : NBLK;
    tp_third_kernel<<<grid, 192>>>(x1, x2, wts, out, Z);
}